// round 1
// baseline (speedup 1.0000x reference)
#include <cuda_runtime.h>

// SparseWindowedAttention: B=1, S=4096, E=768, H=12, hd=64, window=128
//
// Pipeline:
//   1) g_qkv[S,2304]  = x @ Wqkv^T + bqkv            (GEMM, NT, fp32)
//   2) g_attn[S,768]  = windowed softmax attention    (per (head, 64-query block))
//   3) out[S,768]     = g_attn @ Wo^T + bo            (GEMM, NT, fp32)

#define S_LEN 4096
#define EDIM  768
#define NH    12
#define HD    64
#define QKVN  2304
#define WIN   128
#define NKB   5          // key blocks covering [q0-128, q0+63+128] = 320 = 5*64
#define SPAD  320        // padded score row width

__device__ float g_qkv[(size_t)S_LEN * QKVN];   // ~37.7 MB scratch
__device__ float g_attn[(size_t)S_LEN * EDIM];  // ~12.6 MB scratch

// ---------------------------------------------------------------------------
// C[M,N] = A[M,K] @ B[N,K]^T + bias[N]   (both operands K-contiguous)
// Tile: BM=BN=128, BK=16, 256 threads, 8x8 register micro-tile.
// Requires M%128==0, N%128==0, K%16==0 (true for all our shapes).
// ---------------------------------------------------------------------------
__global__ __launch_bounds__(256) void gemm_nt_bias_kernel(
    const float* __restrict__ A, const float* __restrict__ B,
    const float* __restrict__ bias, float* __restrict__ C,
    int M, int N, int K)
{
    __shared__ float As[16][128];
    __shared__ float Bs[16][128];

    const int tid = threadIdx.x;
    const int tx  = tid & 15;
    const int ty  = tid >> 4;
    const int bm  = blockIdx.y * 128;
    const int bn  = blockIdx.x * 128;
    const int lr  = tid >> 2;          // 0..63  (load row)
    const int lc  = (tid & 3) << 2;    // 0,4,8,12 (load col group)

    const float* Aptr = A + (size_t)(bm + lr) * K + lc;
    const float* Bptr = B + (size_t)(bn + lr) * K + lc;

    float acc[8][8];
    #pragma unroll
    for (int i = 0; i < 8; i++)
        #pragma unroll
        for (int j = 0; j < 8; j++) acc[i][j] = 0.f;

    for (int k0 = 0; k0 < K; k0 += 16) {
        float4 a0 = *(const float4*)(Aptr + k0);
        float4 a1 = *(const float4*)(Aptr + (size_t)64 * K + k0);
        float4 b0 = *(const float4*)(Bptr + k0);
        float4 b1 = *(const float4*)(Bptr + (size_t)64 * K + k0);

        __syncthreads();   // protect previous iteration's smem reads
        As[lc+0][lr]    = a0.x; As[lc+1][lr]    = a0.y; As[lc+2][lr]    = a0.z; As[lc+3][lr]    = a0.w;
        As[lc+0][lr+64] = a1.x; As[lc+1][lr+64] = a1.y; As[lc+2][lr+64] = a1.z; As[lc+3][lr+64] = a1.w;
        Bs[lc+0][lr]    = b0.x; Bs[lc+1][lr]    = b0.y; Bs[lc+2][lr]    = b0.z; Bs[lc+3][lr]    = b0.w;
        Bs[lc+0][lr+64] = b1.x; Bs[lc+1][lr+64] = b1.y; Bs[lc+2][lr+64] = b1.z; Bs[lc+3][lr+64] = b1.w;
        __syncthreads();

        #pragma unroll
        for (int k = 0; k < 16; k++) {
            float ra[8], rb[8];
            *(float4*)&ra[0] = *(const float4*)&As[k][ty * 8];
            *(float4*)&ra[4] = *(const float4*)&As[k][ty * 8 + 4];
            *(float4*)&rb[0] = *(const float4*)&Bs[k][tx * 8];
            *(float4*)&rb[4] = *(const float4*)&Bs[k][tx * 8 + 4];
            #pragma unroll
            for (int i = 0; i < 8; i++)
                #pragma unroll
                for (int j = 0; j < 8; j++)
                    acc[i][j] += ra[i] * rb[j];
        }
    }

    #pragma unroll
    for (int i = 0; i < 8; i++) {
        int row = bm + ty * 8 + i;
        #pragma unroll
        for (int j = 0; j < 8; j += 4) {
            int col = bn + tx * 8 + j;
            float4 v;
            v.x = acc[i][j+0] + bias[col+0];
            v.y = acc[i][j+1] + bias[col+1];
            v.z = acc[i][j+2] + bias[col+2];
            v.w = acc[i][j+3] + bias[col+3];
            *(float4*)(C + (size_t)row * N + col) = v;
        }
    }
}

// ---------------------------------------------------------------------------
// Windowed attention. Block = (64-query tile, head). 256 threads.
// smem: sQ[64][64] ([d][q]), sKV[64][64], sS[64][320]  -> 112 KB dynamic.
// ---------------------------------------------------------------------------
__global__ __launch_bounds__(256) void attn_kernel(
    const float* __restrict__ qkv, float* __restrict__ aout)
{
    extern __shared__ float sm[];
    float* sQ  = sm;              // [64][64] stored as [d][q]
    float* sKV = sm + 4096;       // K phase: [d][j]; V phase: [j][d]
    float* sS  = sm + 8192;       // [64][SPAD]

    const int tid = threadIdx.x;
    const int tx  = tid & 15;
    const int ty  = tid >> 4;
    const int h   = blockIdx.y;
    const int q0  = blockIdx.x * 64;
    const int lr  = tid >> 4;          // 0..15
    const int lc  = (tid & 15) << 2;   // 0..60

    // ---- load Q tile (scaled by 1/sqrt(64)) transposed into sQ[d][q] ----
    #pragma unroll
    for (int rr = 0; rr < 4; rr++) {
        int row = rr * 16 + lr;
        float4 v = *(const float4*)&qkv[(size_t)(q0 + row) * QKVN + h * 192 + lc];
        sQ[(lc+0)*64 + row] = v.x * 0.125f;
        sQ[(lc+1)*64 + row] = v.y * 0.125f;
        sQ[(lc+2)*64 + row] = v.z * 0.125f;
        sQ[(lc+3)*64 + row] = v.w * 0.125f;
    }

    // ---- phase 1: scores S = Q K^T, masked, into sS ----
    for (int kb = 0; kb < NKB; kb++) {
        int jbase = q0 - WIN + kb * 64;
        __syncthreads();
        #pragma unroll
        for (int rr = 0; rr < 4; rr++) {
            int j = rr * 16 + lr;
            int g = jbase + j;
            float4 v = make_float4(0.f, 0.f, 0.f, 0.f);
            if (g >= 0 && g < S_LEN)
                v = *(const float4*)&qkv[(size_t)g * QKVN + h * 192 + 64 + lc];
            sKV[(lc+0)*64 + j] = v.x;
            sKV[(lc+1)*64 + j] = v.y;
            sKV[(lc+2)*64 + j] = v.z;
            sKV[(lc+3)*64 + j] = v.w;
        }
        __syncthreads();

        float acc[4][4];
        #pragma unroll
        for (int i = 0; i < 4; i++)
            #pragma unroll
            for (int j = 0; j < 4; j++) acc[i][j] = 0.f;

        #pragma unroll 8
        for (int d = 0; d < 64; d++) {
            float4 ra = *(const float4*)&sQ[d * 64 + ty * 4];
            float4 rb = *(const float4*)&sKV[d * 64 + tx * 4];
            float a[4] = {ra.x, ra.y, ra.z, ra.w};
            float b[4] = {rb.x, rb.y, rb.z, rb.w};
            #pragma unroll
            for (int i = 0; i < 4; i++)
                #pragma unroll
                for (int j = 0; j < 4; j++)
                    acc[i][j] += a[i] * b[j];
        }

        #pragma unroll
        for (int i = 0; i < 4; i++) {
            int qi = q0 + ty * 4 + i;
            #pragma unroll
            for (int jj = 0; jj < 4; jj++) {
                int g = jbase + tx * 4 + jj;
                int diff = qi - g;
                bool ok = (g >= 0) && (g < S_LEN) && (diff <= WIN) && (diff >= -WIN);
                sS[(ty*4 + i) * SPAD + kb * 64 + tx * 4 + jj] = ok ? acc[i][jj] : -1e30f;
            }
        }
    }
    __syncthreads();

    // ---- softmax: each warp handles 8 rows ----
    {
        int wid = tid >> 5, lane = tid & 31;
        for (int rr = 0; rr < 8; rr++) {
            float* row = sS + (wid * 8 + rr) * SPAD;
            float m = -1e30f;
            for (int c = lane; c < SPAD; c += 32) m = fmaxf(m, row[c]);
            #pragma unroll
            for (int o = 16; o > 0; o >>= 1) m = fmaxf(m, __shfl_xor_sync(0xffffffffu, m, o));
            float s = 0.f;
            for (int c = lane; c < SPAD; c += 32) {
                float e = __expf(row[c] - m);
                row[c] = e;
                s += e;
            }
            #pragma unroll
            for (int o = 16; o > 0; o >>= 1) s += __shfl_xor_sync(0xffffffffu, s, o);
            float inv = 1.0f / s;
            for (int c = lane; c < SPAD; c += 32) row[c] *= inv;
        }
    }

    // ---- phase 2: O = P V ----
    float o[4][4];
    #pragma unroll
    for (int i = 0; i < 4; i++)
        #pragma unroll
        for (int j = 0; j < 4; j++) o[i][j] = 0.f;

    for (int kb = 0; kb < NKB; kb++) {
        int jbase = q0 - WIN + kb * 64;
        __syncthreads();
        #pragma unroll
        for (int rr = 0; rr < 4; rr++) {
            int j = rr * 16 + lr;
            int g = jbase + j;
            float4 v = make_float4(0.f, 0.f, 0.f, 0.f);
            if (g >= 0 && g < S_LEN)
                v = *(const float4*)&qkv[(size_t)g * QKVN + h * 192 + 128 + lc];
            *(float4*)&sKV[j * 64 + lc] = v;    // [j][d]
        }
        __syncthreads();

        #pragma unroll 8
        for (int j = 0; j < 64; j++) {
            float4 rv = *(const float4*)&sKV[j * 64 + tx * 4];
            float v[4] = {rv.x, rv.y, rv.z, rv.w};
            #pragma unroll
            for (int i = 0; i < 4; i++) {
                float p = sS[(ty*4 + i) * SPAD + kb * 64 + j];
                #pragma unroll
                for (int jj = 0; jj < 4; jj++)
                    o[i][jj] += p * v[jj];
            }
        }
    }

    #pragma unroll
    for (int i = 0; i < 4; i++) {
        int row = q0 + ty * 4 + i;
        float4 v = make_float4(o[i][0], o[i][1], o[i][2], o[i][3]);
        *(float4*)&aout[(size_t)row * EDIM + h * HD + tx * 4] = v;
    }
}

// ---------------------------------------------------------------------------
extern "C" void kernel_launch(void* const* d_in, const int* in_sizes, int n_in,
                              void* d_out, int out_size)
{
    const float* x    = (const float*)d_in[0];
    const float* Wqkv = (const float*)d_in[1];
    const float* bqkv = (const float*)d_in[2];
    const float* Wo   = (const float*)d_in[3];
    const float* bo   = (const float*)d_in[4];
    float* out = (float*)d_out;

    float *qkv_ptr, *attn_ptr;
    cudaGetSymbolAddress((void**)&qkv_ptr,  g_qkv);
    cudaGetSymbolAddress((void**)&attn_ptr, g_attn);

    const int ATTN_SMEM = (4096 + 4096 + 64 * SPAD) * 4;   // 112 KB
    cudaFuncSetAttribute(attn_kernel, cudaFuncAttributeMaxDynamicSharedMemorySize, ATTN_SMEM);

    // 1) QKV projection
    gemm_nt_bias_kernel<<<dim3(QKVN / 128, S_LEN / 128), 256>>>(
        x, Wqkv, bqkv, qkv_ptr, S_LEN, QKVN, EDIM);

    // 2) Windowed attention
    attn_kernel<<<dim3(S_LEN / 64, NH), 256, ATTN_SMEM>>>(qkv_ptr, attn_ptr);

    // 3) Output projection
    gemm_nt_bias_kernel<<<dim3(EDIM / 128, S_LEN / 128), 256>>>(
        attn_ptr, Wo, bo, out, S_LEN, EDIM, EDIM);
}

// round 3
// speedup vs baseline: 1.6468x; 1.6468x over previous
#include <cuda_runtime.h>
#include <cuda_bf16.h>
#include <cstdint>

// SparseWindowedAttention: B=1, S=4096, E=768, H=12, hd=64, window=128
// R3: GEMMs on mma.sync (HMMA) bf16 with 2-way split compensation (3 passes),
//     cp.async double-buffered pipeline. tcgen05 is not reachable via this
//     toolchain (PTX targets base sm_103).

#define S_LEN 4096
#define EDIM  768
#define NH    12
#define HD    64
#define QKVN  2304
#define WIN   128
#define NKB   5
#define SPAD  320

// ------------------------- scratch -------------------------
__device__ float g_qkv[(size_t)S_LEN * QKVN];
__device__ float g_attn[(size_t)S_LEN * EDIM];
__device__ __nv_bfloat16 g_xhi[(size_t)S_LEN * EDIM];
__device__ __nv_bfloat16 g_xlo[(size_t)S_LEN * EDIM];
__device__ __nv_bfloat16 g_wqhi[(size_t)QKVN * EDIM];
__device__ __nv_bfloat16 g_wqlo[(size_t)QKVN * EDIM];
__device__ __nv_bfloat16 g_wohi[(size_t)EDIM * EDIM];
__device__ __nv_bfloat16 g_wolo[(size_t)EDIM * EDIM];
__device__ __nv_bfloat16 g_ahi[(size_t)S_LEN * EDIM];
__device__ __nv_bfloat16 g_alo[(size_t)S_LEN * EDIM];

// ------------------------- helpers -------------------------
__device__ __forceinline__ uint32_t smem_u32(const void* p) {
    uint32_t a;
    asm("{ .reg .u64 t; cvta.to.shared.u64 t, %1; cvt.u32.u64 %0, t; }" : "=r"(a) : "l"(p));
    return a;
}

#define CP_ASYNC16(saddr, gptr) \
    asm volatile("cp.async.cg.shared.global [%0], [%1], 16;" :: "r"(saddr), "l"(gptr))
#define CP_COMMIT() asm volatile("cp.async.commit_group;")
#define CP_WAIT1()  asm volatile("cp.async.wait_group 1;")
#define CP_WAIT0()  asm volatile("cp.async.wait_group 0;")

__device__ __forceinline__ void ldsm_x4(uint32_t* r, uint32_t addr) {
    asm volatile("ldmatrix.sync.aligned.m8n8.x4.shared.b16 {%0,%1,%2,%3}, [%4];"
                 : "=r"(r[0]), "=r"(r[1]), "=r"(r[2]), "=r"(r[3]) : "r"(addr));
}
__device__ __forceinline__ void ldsm_x2(uint32_t* r, uint32_t addr) {
    asm volatile("ldmatrix.sync.aligned.m8n8.x2.shared.b16 {%0,%1}, [%2];"
                 : "=r"(r[0]), "=r"(r[1]) : "r"(addr));
}
__device__ __forceinline__ void mma_bf16(float* d, const uint32_t* a, const uint32_t* b) {
    asm volatile(
        "mma.sync.aligned.m16n8k16.row.col.f32.bf16.bf16.f32 "
        "{%0,%1,%2,%3}, {%4,%5,%6,%7}, {%8,%9}, {%0,%1,%2,%3};"
        : "+f"(d[0]), "+f"(d[1]), "+f"(d[2]), "+f"(d[3])
        : "r"(a[0]), "r"(a[1]), "r"(a[2]), "r"(a[3]), "r"(b[0]), "r"(b[1]));
}

// ---------------------------------------------------------------------------
// split: fp32 -> (hi, lo) bf16 pair such that x ~= hi + lo
// ---------------------------------------------------------------------------
__global__ void split_bf16_kernel(const float4* __restrict__ in,
                                  __nv_bfloat162* __restrict__ hi,
                                  __nv_bfloat162* __restrict__ lo, int n4)
{
    int i = blockIdx.x * blockDim.x + threadIdx.x;
    if (i >= n4) return;
    float4 v = in[i];
    __nv_bfloat16 h0 = __float2bfloat16(v.x), h1 = __float2bfloat16(v.y);
    __nv_bfloat16 h2 = __float2bfloat16(v.z), h3 = __float2bfloat16(v.w);
    __nv_bfloat16 l0 = __float2bfloat16(v.x - __bfloat162float(h0));
    __nv_bfloat16 l1 = __float2bfloat16(v.y - __bfloat162float(h1));
    __nv_bfloat16 l2 = __float2bfloat16(v.z - __bfloat162float(h2));
    __nv_bfloat16 l3 = __float2bfloat16(v.w - __bfloat162float(h3));
    hi[2*i]   = __nv_bfloat162(h0, h1);
    hi[2*i+1] = __nv_bfloat162(h2, h3);
    lo[2*i]   = __nv_bfloat162(l0, l1);
    lo[2*i+1] = __nv_bfloat162(l2, l3);
}

// ---------------------------------------------------------------------------
// C[M,N] = (Ahi+Alo)[M,K] @ (Bhi+Blo)[N,K]^T + bias  via mma.sync bf16 3-pass.
// 128x128 CTA tile, BK=32, 256 threads = 8 warps in 2(M)x4(N), warp = 64x32.
// smem rows padded to 40 bf16 (80B) -> conflict-free ldmatrix phases.
// cp.async double-buffered.
// ---------------------------------------------------------------------------
#define ROWPAD 40                       // elements per smem row
#define TILEB  (128 * ROWPAD * 2)       // 10240 B per matrix tile
#define BUFB   (4 * TILEB)              // AHI|ALO|BHI|BLO

__global__ __launch_bounds__(256) void gemm_tc_kernel(
    const __nv_bfloat16* __restrict__ Ahi, const __nv_bfloat16* __restrict__ Alo,
    const __nv_bfloat16* __restrict__ Bhi, const __nv_bfloat16* __restrict__ Blo,
    const float* __restrict__ bias, float* __restrict__ C,
    int M, int N, int K)
{
    extern __shared__ char smem[];
    const uint32_t sbase = smem_u32(smem);

    const int tid  = threadIdx.x;
    const int wid  = tid >> 5;
    const int lane = tid & 31;
    const int bm = blockIdx.y * 128;
    const int bn = blockIdx.x * 128;
    const int nch = K >> 5;             // K / 32

    const int warp_m = wid & 1;         // 0..1  (64 rows each)
    const int warp_n = wid >> 1;        // 0..3  (32 cols each)

    // load mapping: 2 chunks of 16B per thread per matrix
    const int r0 = tid >> 2;            // chunk 0 row (0..63)
    const int c0 = tid & 3;             // chunk 0 col group
    const int r1 = r0 + 64;             // chunk 1 row

    float acc[4][4][4];
    #pragma unroll
    for (int i = 0; i < 4; i++)
        #pragma unroll
        for (int j = 0; j < 4; j++)
            #pragma unroll
            for (int e = 0; e < 4; e++) acc[i][j][e] = 0.f;

    // --- cp.async tile loader ---
    auto load_tiles = [&](int t, int buf) {
        const uint32_t sb = sbase + buf * BUFB;
        const int kelem = t * 32 + c0 * 8;
        const uint32_t so0 = (uint32_t)(r0 * ROWPAD + c0 * 8) * 2;
        const uint32_t so1 = (uint32_t)(r1 * ROWPAD + c0 * 8) * 2;
        const __nv_bfloat16* pa0 = Ahi + (size_t)(bm + r0) * K + kelem;
        const __nv_bfloat16* pa1 = Ahi + (size_t)(bm + r1) * K + kelem;
        const __nv_bfloat16* pb0 = Bhi + (size_t)(bn + r0) * K + kelem;
        const __nv_bfloat16* pb1 = Bhi + (size_t)(bn + r1) * K + kelem;
        const __nv_bfloat16* qa0 = Alo + (size_t)(bm + r0) * K + kelem;
        const __nv_bfloat16* qa1 = Alo + (size_t)(bm + r1) * K + kelem;
        const __nv_bfloat16* qb0 = Blo + (size_t)(bn + r0) * K + kelem;
        const __nv_bfloat16* qb1 = Blo + (size_t)(bn + r1) * K + kelem;
        CP_ASYNC16(sb + 0*TILEB + so0, pa0);
        CP_ASYNC16(sb + 0*TILEB + so1, pa1);
        CP_ASYNC16(sb + 1*TILEB + so0, qa0);
        CP_ASYNC16(sb + 1*TILEB + so1, qa1);
        CP_ASYNC16(sb + 2*TILEB + so0, pb0);
        CP_ASYNC16(sb + 2*TILEB + so1, pb1);
        CP_ASYNC16(sb + 3*TILEB + so0, qb0);
        CP_ASYNC16(sb + 3*TILEB + so1, qb1);
    };

    load_tiles(0, 0);
    CP_COMMIT();

    for (int t = 0; t < nch; t++) {
        if (t + 1 < nch) {
            load_tiles(t + 1, (t + 1) & 1);
            CP_COMMIT();
            CP_WAIT1();
        } else {
            CP_WAIT0();
        }
        __syncthreads();

        const uint32_t sb = sbase + (t & 1) * BUFB;
        // ldmatrix thread addressing
        const int la_row = lane & 15;           // A: row within 16
        const int la_kh  = lane >> 4;           // A: k half (0/1)
        const int lb_row = lane & 7;            // B: row within 8
        const int lb_kh  = (lane >> 3) & 1;     // B: k half

        #pragma unroll
        for (int ks = 0; ks < 2; ks++) {
            uint32_t ahi[4][4], alo[4][4], bhi[4][2], blo[4][2];
            #pragma unroll
            for (int mi = 0; mi < 4; mi++) {
                const int row = warp_m * 64 + mi * 16 + la_row;
                const uint32_t off = (uint32_t)(row * ROWPAD + ks * 16 + la_kh * 8) * 2;
                ldsm_x4(ahi[mi], sb + 0*TILEB + off);
                ldsm_x4(alo[mi], sb + 1*TILEB + off);
            }
            #pragma unroll
            for (int ni = 0; ni < 4; ni++) {
                const int row = warp_n * 32 + ni * 8 + lb_row;
                const uint32_t off = (uint32_t)(row * ROWPAD + ks * 16 + lb_kh * 8) * 2;
                ldsm_x2(bhi[ni], sb + 2*TILEB + off);
                ldsm_x2(blo[ni], sb + 3*TILEB + off);
            }
            #pragma unroll
            for (int mi = 0; mi < 4; mi++)
                #pragma unroll
                for (int ni = 0; ni < 4; ni++) {
                    mma_bf16(acc[mi][ni], ahi[mi], bhi[ni]);
                    mma_bf16(acc[mi][ni], alo[mi], bhi[ni]);
                    mma_bf16(acc[mi][ni], ahi[mi], blo[ni]);
                }
        }
        __syncthreads();
    }

    // epilogue: c frag (row = lane/4 [+8], col = (lane%4)*2)
    #pragma unroll
    for (int mi = 0; mi < 4; mi++) {
        const int row = bm + warp_m * 64 + mi * 16 + (lane >> 2);
        #pragma unroll
        for (int ni = 0; ni < 4; ni++) {
            const int col = bn + warp_n * 32 + ni * 8 + (lane & 3) * 2;
            const float2 bv = *(const float2*)(bias + col);
            float2 v0 = make_float2(acc[mi][ni][0] + bv.x, acc[mi][ni][1] + bv.y);
            float2 v1 = make_float2(acc[mi][ni][2] + bv.x, acc[mi][ni][3] + bv.y);
            *(float2*)(C + (size_t)row * N + col)       = v0;
            *(float2*)(C + (size_t)(row + 8) * N + col) = v1;
        }
    }
}

// ---------------------------------------------------------------------------
// Windowed attention (unchanged from R1). Block = (64-query tile, head).
// ---------------------------------------------------------------------------
__global__ __launch_bounds__(256) void attn_kernel(
    const float* __restrict__ qkv, float* __restrict__ aout)
{
    extern __shared__ float sm[];
    float* sQ  = sm;
    float* sKV = sm + 4096;
    float* sS  = sm + 8192;

    const int tid = threadIdx.x;
    const int tx  = tid & 15;
    const int ty  = tid >> 4;
    const int h   = blockIdx.y;
    const int q0  = blockIdx.x * 64;
    const int lr  = tid >> 4;
    const int lc  = (tid & 15) << 2;

    #pragma unroll
    for (int rr = 0; rr < 4; rr++) {
        int row = rr * 16 + lr;
        float4 v = *(const float4*)&qkv[(size_t)(q0 + row) * QKVN + h * 192 + lc];
        sQ[(lc+0)*64 + row] = v.x * 0.125f;
        sQ[(lc+1)*64 + row] = v.y * 0.125f;
        sQ[(lc+2)*64 + row] = v.z * 0.125f;
        sQ[(lc+3)*64 + row] = v.w * 0.125f;
    }

    for (int kb = 0; kb < NKB; kb++) {
        int jbase = q0 - WIN + kb * 64;
        __syncthreads();
        #pragma unroll
        for (int rr = 0; rr < 4; rr++) {
            int j = rr * 16 + lr;
            int g = jbase + j;
            float4 v = make_float4(0.f, 0.f, 0.f, 0.f);
            if (g >= 0 && g < S_LEN)
                v = *(const float4*)&qkv[(size_t)g * QKVN + h * 192 + 64 + lc];
            sKV[(lc+0)*64 + j] = v.x;
            sKV[(lc+1)*64 + j] = v.y;
            sKV[(lc+2)*64 + j] = v.z;
            sKV[(lc+3)*64 + j] = v.w;
        }
        __syncthreads();

        float acc[4][4];
        #pragma unroll
        for (int i = 0; i < 4; i++)
            #pragma unroll
            for (int j = 0; j < 4; j++) acc[i][j] = 0.f;

        #pragma unroll 8
        for (int d = 0; d < 64; d++) {
            float4 ra = *(const float4*)&sQ[d * 64 + ty * 4];
            float4 rb = *(const float4*)&sKV[d * 64 + tx * 4];
            float a[4] = {ra.x, ra.y, ra.z, ra.w};
            float b[4] = {rb.x, rb.y, rb.z, rb.w};
            #pragma unroll
            for (int i = 0; i < 4; i++)
                #pragma unroll
                for (int j = 0; j < 4; j++)
                    acc[i][j] += a[i] * b[j];
        }

        #pragma unroll
        for (int i = 0; i < 4; i++) {
            int qi = q0 + ty * 4 + i;
            #pragma unroll
            for (int jj = 0; jj < 4; jj++) {
                int g = jbase + tx * 4 + jj;
                int diff = qi - g;
                bool ok = (g >= 0) && (g < S_LEN) && (diff <= WIN) && (diff >= -WIN);
                sS[(ty*4 + i) * SPAD + kb * 64 + tx * 4 + jj] = ok ? acc[i][jj] : -1e30f;
            }
        }
    }
    __syncthreads();

    {
        int wid = tid >> 5, lane = tid & 31;
        for (int rr = 0; rr < 8; rr++) {
            float* row = sS + (wid * 8 + rr) * SPAD;
            float m = -1e30f;
            for (int c = lane; c < SPAD; c += 32) m = fmaxf(m, row[c]);
            #pragma unroll
            for (int o = 16; o > 0; o >>= 1) m = fmaxf(m, __shfl_xor_sync(0xffffffffu, m, o));
            float s = 0.f;
            for (int c = lane; c < SPAD; c += 32) {
                float e = __expf(row[c] - m);
                row[c] = e;
                s += e;
            }
            #pragma unroll
            for (int o = 16; o > 0; o >>= 1) s += __shfl_xor_sync(0xffffffffu, s, o);
            float inv = 1.0f / s;
            for (int c = lane; c < SPAD; c += 32) row[c] *= inv;
        }
    }

    float o[4][4];
    #pragma unroll
    for (int i = 0; i < 4; i++)
        #pragma unroll
        for (int j = 0; j < 4; j++) o[i][j] = 0.f;

    for (int kb = 0; kb < NKB; kb++) {
        int jbase = q0 - WIN + kb * 64;
        __syncthreads();
        #pragma unroll
        for (int rr = 0; rr < 4; rr++) {
            int j = rr * 16 + lr;
            int g = jbase + j;
            float4 v = make_float4(0.f, 0.f, 0.f, 0.f);
            if (g >= 0 && g < S_LEN)
                v = *(const float4*)&qkv[(size_t)g * QKVN + h * 192 + 128 + lc];
            *(float4*)&sKV[j * 64 + lc] = v;
        }
        __syncthreads();

        #pragma unroll 8
        for (int j = 0; j < 64; j++) {
            float4 rv = *(const float4*)&sKV[j * 64 + tx * 4];
            float v[4] = {rv.x, rv.y, rv.z, rv.w};
            #pragma unroll
            for (int i = 0; i < 4; i++) {
                float p = sS[(ty*4 + i) * SPAD + kb * 64 + j];
                #pragma unroll
                for (int jj = 0; jj < 4; jj++)
                    o[i][jj] += p * v[jj];
            }
        }
    }

    #pragma unroll
    for (int i = 0; i < 4; i++) {
        int row = q0 + ty * 4 + i;
        float4 v = make_float4(o[i][0], o[i][1], o[i][2], o[i][3]);
        *(float4*)&aout[(size_t)row * EDIM + h * HD + tx * 4] = v;
    }
}

// ---------------------------------------------------------------------------
extern "C" void kernel_launch(void* const* d_in, const int* in_sizes, int n_in,
                              void* d_out, int out_size)
{
    const float* x    = (const float*)d_in[0];
    const float* Wqkv = (const float*)d_in[1];
    const float* bqkv = (const float*)d_in[2];
    const float* Wo   = (const float*)d_in[3];
    const float* bo   = (const float*)d_in[4];
    float* out = (float*)d_out;

    float *qkv_ptr, *attn_ptr;
    __nv_bfloat16 *xhi, *xlo, *wqhi, *wqlo, *wohi, *wolo, *ahi, *alo;
    cudaGetSymbolAddress((void**)&qkv_ptr,  g_qkv);
    cudaGetSymbolAddress((void**)&attn_ptr, g_attn);
    cudaGetSymbolAddress((void**)&xhi,  g_xhi);
    cudaGetSymbolAddress((void**)&xlo,  g_xlo);
    cudaGetSymbolAddress((void**)&wqhi, g_wqhi);
    cudaGetSymbolAddress((void**)&wqlo, g_wqlo);
    cudaGetSymbolAddress((void**)&wohi, g_wohi);
    cudaGetSymbolAddress((void**)&wolo, g_wolo);
    cudaGetSymbolAddress((void**)&ahi,  g_ahi);
    cudaGetSymbolAddress((void**)&alo,  g_alo);

    const int GEMM_SMEM = 2 * BUFB;     // 81920
    cudaFuncSetAttribute(gemm_tc_kernel, cudaFuncAttributeMaxDynamicSharedMemorySize, GEMM_SMEM);
    const int ATTN_SMEM = (4096 + 4096 + 64 * SPAD) * 4;
    cudaFuncSetAttribute(attn_kernel, cudaFuncAttributeMaxDynamicSharedMemorySize, ATTN_SMEM);

    {
        int n4 = (S_LEN * EDIM) / 4;
        split_bf16_kernel<<<(n4 + 255) / 256, 256>>>(
            (const float4*)x, (__nv_bfloat162*)xhi, (__nv_bfloat162*)xlo, n4);
    }
    {
        int n4 = (QKVN * EDIM) / 4;
        split_bf16_kernel<<<(n4 + 255) / 256, 256>>>(
            (const float4*)Wqkv, (__nv_bfloat162*)wqhi, (__nv_bfloat162*)wqlo, n4);
    }
    {
        int n4 = (EDIM * EDIM) / 4;
        split_bf16_kernel<<<(n4 + 255) / 256, 256>>>(
            (const float4*)Wo, (__nv_bfloat162*)wohi, (__nv_bfloat162*)wolo, n4);
    }

    // 1) QKV projection (tensor cores via mma.sync)
    gemm_tc_kernel<<<dim3(QKVN / 128, S_LEN / 128), 256, GEMM_SMEM>>>(
        xhi, xlo, wqhi, wqlo, bqkv, qkv_ptr, S_LEN, QKVN, EDIM);

    // 2) windowed attention (fp32 SIMT)
    attn_kernel<<<dim3(S_LEN / 64, NH), 256, ATTN_SMEM>>>(qkv_ptr, attn_ptr);

    // split attention output
    {
        int n4 = (S_LEN * EDIM) / 4;
        split_bf16_kernel<<<(n4 + 255) / 256, 256>>>(
            (const float4*)attn_ptr, (__nv_bfloat162*)ahi, (__nv_bfloat162*)alo, n4);
    }

    // 3) output projection
    gemm_tc_kernel<<<dim3(EDIM / 128, S_LEN / 128), 256, GEMM_SMEM>>>(
        ahi, alo, wohi, wolo, bo, out, S_LEN, EDIM, EDIM);
}

// round 4
// speedup vs baseline: 2.3291x; 1.4144x over previous
#include <cuda_runtime.h>
#include <cuda_bf16.h>
#include <cstdint>

// SparseWindowedAttention: B=1, S=4096, E=768, H=12, hd=64, window=128
// R4: flash-style tensor-core attention (mma.sync bf16, 3-pass split comp,
//     register-resident P), GEMM1 writes bf16 hi/lo directly.

#define S_LEN 4096
#define EDIM  768
#define NH    12
#define HD    64
#define QKVN  2304
#define WIN   128

// ------------------------- scratch -------------------------
__device__ __nv_bfloat16 g_xhi[(size_t)S_LEN * EDIM];
__device__ __nv_bfloat16 g_xlo[(size_t)S_LEN * EDIM];
__device__ __nv_bfloat16 g_wqhi[(size_t)QKVN * EDIM];
__device__ __nv_bfloat16 g_wqlo[(size_t)QKVN * EDIM];
__device__ __nv_bfloat16 g_wohi[(size_t)EDIM * EDIM];
__device__ __nv_bfloat16 g_wolo[(size_t)EDIM * EDIM];
__device__ __nv_bfloat16 g_qkvhi[(size_t)S_LEN * QKVN];
__device__ __nv_bfloat16 g_qkvlo[(size_t)S_LEN * QKVN];
__device__ __nv_bfloat16 g_ahi[(size_t)S_LEN * EDIM];
__device__ __nv_bfloat16 g_alo[(size_t)S_LEN * EDIM];

// ------------------------- helpers -------------------------
__device__ __forceinline__ uint32_t smem_u32(const void* p) {
    uint32_t a;
    asm("{ .reg .u64 t; cvta.to.shared.u64 t, %1; cvt.u32.u64 %0, t; }" : "=r"(a) : "l"(p));
    return a;
}

#define CP_ASYNC16(saddr, gptr) \
    asm volatile("cp.async.cg.shared.global [%0], [%1], 16;" :: "r"(saddr), "l"(gptr))
#define CP_COMMIT() asm volatile("cp.async.commit_group;")
#define CP_WAIT1()  asm volatile("cp.async.wait_group 1;")
#define CP_WAIT0()  asm volatile("cp.async.wait_group 0;")

__device__ __forceinline__ void ldsm_x4(uint32_t* r, uint32_t addr) {
    asm volatile("ldmatrix.sync.aligned.m8n8.x4.shared.b16 {%0,%1,%2,%3}, [%4];"
                 : "=r"(r[0]), "=r"(r[1]), "=r"(r[2]), "=r"(r[3]) : "r"(addr));
}
__device__ __forceinline__ void ldsm_x2(uint32_t* r, uint32_t addr) {
    asm volatile("ldmatrix.sync.aligned.m8n8.x2.shared.b16 {%0,%1}, [%2];"
                 : "=r"(r[0]), "=r"(r[1]) : "r"(addr));
}
__device__ __forceinline__ void ldsm_x2_trans(uint32_t* r, uint32_t addr) {
    asm volatile("ldmatrix.sync.aligned.m8n8.x2.trans.shared.b16 {%0,%1}, [%2];"
                 : "=r"(r[0]), "=r"(r[1]) : "r"(addr));
}
__device__ __forceinline__ void mma_bf16(float* d, const uint32_t* a, const uint32_t* b) {
    asm volatile(
        "mma.sync.aligned.m16n8k16.row.col.f32.bf16.bf16.f32 "
        "{%0,%1,%2,%3}, {%4,%5,%6,%7}, {%8,%9}, {%0,%1,%2,%3};"
        : "+f"(d[0]), "+f"(d[1]), "+f"(d[2]), "+f"(d[3])
        : "r"(a[0]), "r"(a[1]), "r"(a[2]), "r"(a[3]), "r"(b[0]), "r"(b[1]));
}

// split two floats into packed bf16x2 (hi, lo) with x = hi + lo compensation
__device__ __forceinline__ void split2(float x, float y, uint32_t& hi, uint32_t& lo) {
    __nv_bfloat16 hx = __float2bfloat16(x);
    __nv_bfloat16 hy = __float2bfloat16(y);
    __nv_bfloat16 lx = __float2bfloat16(x - __bfloat162float(hx));
    __nv_bfloat16 ly = __float2bfloat16(y - __bfloat162float(hy));
    hi = ((uint32_t)__bfloat16_as_ushort(hy) << 16) | (uint32_t)__bfloat16_as_ushort(hx);
    lo = ((uint32_t)__bfloat16_as_ushort(ly) << 16) | (uint32_t)__bfloat16_as_ushort(lx);
}

// ---------------------------------------------------------------------------
// split: fp32 -> (hi, lo) bf16 arrays
// ---------------------------------------------------------------------------
__global__ void split_bf16_kernel(const float4* __restrict__ in,
                                  __nv_bfloat162* __restrict__ hi,
                                  __nv_bfloat162* __restrict__ lo, int n4)
{
    int i = blockIdx.x * blockDim.x + threadIdx.x;
    if (i >= n4) return;
    float4 v = in[i];
    uint32_t h0, l0, h1, l1;
    split2(v.x, v.y, h0, l0);
    split2(v.z, v.w, h1, l1);
    ((uint32_t*)hi)[2*i]   = h0;
    ((uint32_t*)hi)[2*i+1] = h1;
    ((uint32_t*)lo)[2*i]   = l0;
    ((uint32_t*)lo)[2*i+1] = l1;
}

// ---------------------------------------------------------------------------
// GEMM: C = (Ahi+Alo)[M,K] @ (Bhi+Blo)[N,K]^T + bias, mma.sync bf16 3-pass.
// Output either fp32 (C) or bf16 hi/lo (Chi/Clo) when Chi != nullptr.
// ---------------------------------------------------------------------------
#define ROWPAD 40
#define TILEB  (128 * ROWPAD * 2)
#define BUFB   (4 * TILEB)

__global__ __launch_bounds__(256) void gemm_tc_kernel(
    const __nv_bfloat16* __restrict__ Ahi, const __nv_bfloat16* __restrict__ Alo,
    const __nv_bfloat16* __restrict__ Bhi, const __nv_bfloat16* __restrict__ Blo,
    const float* __restrict__ bias, float* __restrict__ C,
    __nv_bfloat16* __restrict__ Chi, __nv_bfloat16* __restrict__ Clo,
    int M, int N, int K)
{
    extern __shared__ char smem[];
    const uint32_t sbase = smem_u32(smem);

    const int tid  = threadIdx.x;
    const int wid  = tid >> 5;
    const int lane = tid & 31;
    const int bm = blockIdx.y * 128;
    const int bn = blockIdx.x * 128;
    const int nch = K >> 5;

    const int warp_m = wid & 1;
    const int warp_n = wid >> 1;

    const int r0 = tid >> 2;
    const int c0 = tid & 3;
    const int r1 = r0 + 64;

    float acc[4][4][4];
    #pragma unroll
    for (int i = 0; i < 4; i++)
        #pragma unroll
        for (int j = 0; j < 4; j++)
            #pragma unroll
            for (int e = 0; e < 4; e++) acc[i][j][e] = 0.f;

    auto load_tiles = [&](int t, int buf) {
        const uint32_t sb = sbase + buf * BUFB;
        const int kelem = t * 32 + c0 * 8;
        const uint32_t so0 = (uint32_t)(r0 * ROWPAD + c0 * 8) * 2;
        const uint32_t so1 = (uint32_t)(r1 * ROWPAD + c0 * 8) * 2;
        CP_ASYNC16(sb + 0*TILEB + so0, Ahi + (size_t)(bm + r0) * K + kelem);
        CP_ASYNC16(sb + 0*TILEB + so1, Ahi + (size_t)(bm + r1) * K + kelem);
        CP_ASYNC16(sb + 1*TILEB + so0, Alo + (size_t)(bm + r0) * K + kelem);
        CP_ASYNC16(sb + 1*TILEB + so1, Alo + (size_t)(bm + r1) * K + kelem);
        CP_ASYNC16(sb + 2*TILEB + so0, Bhi + (size_t)(bn + r0) * K + kelem);
        CP_ASYNC16(sb + 2*TILEB + so1, Bhi + (size_t)(bn + r1) * K + kelem);
        CP_ASYNC16(sb + 3*TILEB + so0, Blo + (size_t)(bn + r0) * K + kelem);
        CP_ASYNC16(sb + 3*TILEB + so1, Blo + (size_t)(bn + r1) * K + kelem);
    };

    load_tiles(0, 0);
    CP_COMMIT();

    for (int t = 0; t < nch; t++) {
        if (t + 1 < nch) {
            load_tiles(t + 1, (t + 1) & 1);
            CP_COMMIT();
            CP_WAIT1();
        } else {
            CP_WAIT0();
        }
        __syncthreads();

        const uint32_t sb = sbase + (t & 1) * BUFB;
        const int la_row = lane & 15;
        const int la_kh  = lane >> 4;
        const int lb_row = lane & 7;
        const int lb_kh  = (lane >> 3) & 1;

        #pragma unroll
        for (int ks = 0; ks < 2; ks++) {
            uint32_t ahi[4][4], alo[4][4], bhi[4][2], blo[4][2];
            #pragma unroll
            for (int mi = 0; mi < 4; mi++) {
                const int row = warp_m * 64 + mi * 16 + la_row;
                const uint32_t off = (uint32_t)(row * ROWPAD + ks * 16 + la_kh * 8) * 2;
                ldsm_x4(ahi[mi], sb + 0*TILEB + off);
                ldsm_x4(alo[mi], sb + 1*TILEB + off);
            }
            #pragma unroll
            for (int ni = 0; ni < 4; ni++) {
                const int row = warp_n * 32 + ni * 8 + lb_row;
                const uint32_t off = (uint32_t)(row * ROWPAD + ks * 16 + lb_kh * 8) * 2;
                ldsm_x2(bhi[ni], sb + 2*TILEB + off);
                ldsm_x2(blo[ni], sb + 3*TILEB + off);
            }
            #pragma unroll
            for (int mi = 0; mi < 4; mi++)
                #pragma unroll
                for (int ni = 0; ni < 4; ni++) {
                    mma_bf16(acc[mi][ni], ahi[mi], bhi[ni]);
                    mma_bf16(acc[mi][ni], alo[mi], bhi[ni]);
                    mma_bf16(acc[mi][ni], ahi[mi], blo[ni]);
                }
        }
        __syncthreads();
    }

    #pragma unroll
    for (int mi = 0; mi < 4; mi++) {
        const int row = bm + warp_m * 64 + mi * 16 + (lane >> 2);
        #pragma unroll
        for (int ni = 0; ni < 4; ni++) {
            const int col = bn + warp_n * 32 + ni * 8 + (lane & 3) * 2;
            const float2 bv = *(const float2*)(bias + col);
            float v0 = acc[mi][ni][0] + bv.x, v1 = acc[mi][ni][1] + bv.y;
            float v2 = acc[mi][ni][2] + bv.x, v3 = acc[mi][ni][3] + bv.y;
            if (Chi) {
                uint32_t h0, l0, h1, l1;
                split2(v0, v1, h0, l0);
                split2(v2, v3, h1, l1);
                *(uint32_t*)(Chi + (size_t)row * N + col)       = h0;
                *(uint32_t*)(Clo + (size_t)row * N + col)       = l0;
                *(uint32_t*)(Chi + (size_t)(row + 8) * N + col) = h1;
                *(uint32_t*)(Clo + (size_t)(row + 8) * N + col) = l1;
            } else {
                *(float2*)(C + (size_t)row * N + col)       = make_float2(v0, v1);
                *(float2*)(C + (size_t)(row + 8) * N + col) = make_float2(v2, v3);
            }
        }
    }
}

// ---------------------------------------------------------------------------
// Flash attention on tensor cores. Block = (64 queries, head), 4 warps.
// smem: Q/K/V tiles bf16 hi/lo, row pitch 72 (144B). 55296 B total.
// ---------------------------------------------------------------------------
#define QPITCH 72
#define SQHI 0
#define SQLO 9216
#define SKHI 18432
#define SKLO 27648
#define SVHI 36864
#define SVLO 46080
#define ATTN_SMEM 55296

__global__ __launch_bounds__(128) void attn_tc_kernel(
    const __nv_bfloat16* __restrict__ qkvhi, const __nv_bfloat16* __restrict__ qkvlo,
    __nv_bfloat16* __restrict__ ahi, __nv_bfloat16* __restrict__ alo)
{
    extern __shared__ char smem[];
    const uint32_t sb = smem_u32(smem);

    const int tid  = threadIdx.x;
    const int lane = tid & 31;
    const int wq   = tid >> 5;            // 0..3, 16 q rows each
    const int h    = blockIdx.y;
    const int q0   = blockIdx.x * 64;

    const int lrow = tid >> 1;            // 0..63
    const int half = tid & 1;             // 0..1 (32 elems each)
    const uint32_t soff = (uint32_t)(lrow * QPITCH + half * 32) * 2;

    // ---- load Q tile (hi/lo) ----
    {
        const __nv_bfloat16* sh = qkvhi + (size_t)(q0 + lrow) * QKVN + h * 192 + half * 32;
        const __nv_bfloat16* sl = qkvlo + (size_t)(q0 + lrow) * QKVN + h * 192 + half * 32;
        #pragma unroll
        for (int i = 0; i < 4; i++) {
            *(uint4*)(smem + SQHI + soff + i * 16) = *(const uint4*)(sh + i * 8);
            *(uint4*)(smem + SQLO + soff + i * 16) = *(const uint4*)(sl + i * 8);
        }
    }

    float oacc[8][4];
    #pragma unroll
    for (int ni = 0; ni < 8; ni++)
        #pragma unroll
        for (int e = 0; e < 4; e++) oacc[ni][e] = 0.f;
    float m_a = -1e30f, m_b = -1e30f, l_a = 0.f, l_b = 0.f;

    const int ra = q0 + wq * 16 + (lane >> 2);
    const int rb = ra + 8;

    for (int kb = 0; kb < 5; kb++) {
        const int jbase = q0 - WIN + kb * 64;
        __syncthreads();
        // ---- load K/V tiles (hi/lo), zero-fill OOB ----
        {
            const int g = jbase + lrow;
            const bool v = (g >= 0) && (g < S_LEN);
            const size_t gb = (size_t)(v ? g : 0) * QKVN + h * 192 + half * 32;
            const uint4 z = make_uint4(0, 0, 0, 0);
            #pragma unroll
            for (int i = 0; i < 4; i++) {
                *(uint4*)(smem + SKHI + soff + i*16) = v ? *(const uint4*)(qkvhi + gb + 64  + i*8) : z;
                *(uint4*)(smem + SKLO + soff + i*16) = v ? *(const uint4*)(qkvlo + gb + 64  + i*8) : z;
                *(uint4*)(smem + SVHI + soff + i*16) = v ? *(const uint4*)(qkvhi + gb + 128 + i*8) : z;
                *(uint4*)(smem + SVLO + soff + i*16) = v ? *(const uint4*)(qkvlo + gb + 128 + i*8) : z;
            }
        }
        __syncthreads();

        // ---- QK^T (3-pass) ----
        float sacc[8][4];
        #pragma unroll
        for (int ni = 0; ni < 8; ni++)
            #pragma unroll
            for (int e = 0; e < 4; e++) sacc[ni][e] = 0.f;

        #pragma unroll
        for (int ks = 0; ks < 4; ks++) {
            uint32_t aqh[4], aql[4];
            const uint32_t qoff = (uint32_t)((wq*16 + (lane & 15)) * QPITCH + ks*16 + (lane >> 4) * 8) * 2;
            ldsm_x4(aqh, sb + SQHI + qoff);
            ldsm_x4(aql, sb + SQLO + qoff);
            #pragma unroll
            for (int ni = 0; ni < 8; ni++) {
                uint32_t bh[2], bl[2];
                const uint32_t koff = (uint32_t)((ni*8 + (lane & 7)) * QPITCH + ks*16 + ((lane >> 3) & 1) * 8) * 2;
                ldsm_x2(bh, sb + SKHI + koff);
                ldsm_x2(bl, sb + SKLO + koff);
                mma_bf16(sacc[ni], aqh, bh);
                mma_bf16(sacc[ni], aql, bh);
                mma_bf16(sacc[ni], aqh, bl);
            }
        }

        // ---- mask + scale + online softmax ----
        float mk_a = -1e30f, mk_b = -1e30f;
        #pragma unroll
        for (int ni = 0; ni < 8; ni++) {
            const int j0 = jbase + ni * 8 + (lane & 3) * 2;
            #pragma unroll
            for (int e = 0; e < 4; e++) {
                const int g = j0 + (e & 1);
                const int r = (e < 2) ? ra : rb;
                const int d = r - g;
                const bool ok = (g >= 0) && (g < S_LEN) && (d <= WIN) && (d >= -WIN);
                const float s = ok ? sacc[ni][e] * 0.125f : -1e30f;
                sacc[ni][e] = s;
                if (e < 2) mk_a = fmaxf(mk_a, s); else mk_b = fmaxf(mk_b, s);
            }
        }
        mk_a = fmaxf(mk_a, __shfl_xor_sync(0xffffffffu, mk_a, 1));
        mk_a = fmaxf(mk_a, __shfl_xor_sync(0xffffffffu, mk_a, 2));
        mk_b = fmaxf(mk_b, __shfl_xor_sync(0xffffffffu, mk_b, 1));
        mk_b = fmaxf(mk_b, __shfl_xor_sync(0xffffffffu, mk_b, 2));

        const float mn_a = fmaxf(m_a, mk_a);
        const float mn_b = fmaxf(m_b, mk_b);
        const float corr_a = __expf(m_a - mn_a);
        const float corr_b = __expf(m_b - mn_b);
        const float sm_a = (mn_a < -1e29f) ? 0.f : mn_a;
        const float sm_b = (mn_b < -1e29f) ? 0.f : mn_b;

        float su_a = 0.f, su_b = 0.f;
        #pragma unroll
        for (int ni = 0; ni < 8; ni++) {
            #pragma unroll
            for (int e = 0; e < 4; e++) {
                const float p = __expf(sacc[ni][e] - ((e < 2) ? sm_a : sm_b));
                sacc[ni][e] = p;
                if (e < 2) su_a += p; else su_b += p;
            }
        }
        su_a += __shfl_xor_sync(0xffffffffu, su_a, 1);
        su_a += __shfl_xor_sync(0xffffffffu, su_a, 2);
        su_b += __shfl_xor_sync(0xffffffffu, su_b, 1);
        su_b += __shfl_xor_sync(0xffffffffu, su_b, 2);

        l_a = l_a * corr_a + su_a;
        l_b = l_b * corr_b + su_b;
        m_a = mn_a; m_b = mn_b;

        #pragma unroll
        for (int ni = 0; ni < 8; ni++) {
            oacc[ni][0] *= corr_a; oacc[ni][1] *= corr_a;
            oacc[ni][2] *= corr_b; oacc[ni][3] *= corr_b;
        }

        // ---- P·V (3-pass): P fragments built in registers from sacc ----
        #pragma unroll
        for (int kk = 0; kk < 4; kk++) {
            uint32_t aph[4], apl[4];
            split2(sacc[2*kk][0],   sacc[2*kk][1],   aph[0], apl[0]);
            split2(sacc[2*kk][2],   sacc[2*kk][3],   aph[1], apl[1]);
            split2(sacc[2*kk+1][0], sacc[2*kk+1][1], aph[2], apl[2]);
            split2(sacc[2*kk+1][2], sacc[2*kk+1][3], aph[3], apl[3]);
            #pragma unroll
            for (int ni = 0; ni < 8; ni++) {
                uint32_t bvh[2], bvl[2];
                const uint32_t voff = (uint32_t)((kk*16 + (lane & 15)) * QPITCH + ni * 8) * 2;
                ldsm_x2_trans(bvh, sb + SVHI + voff);
                ldsm_x2_trans(bvl, sb + SVLO + voff);
                mma_bf16(oacc[ni], aph, bvh);
                mma_bf16(oacc[ni], apl, bvh);
                mma_bf16(oacc[ni], aph, bvl);
            }
        }
    }

    // ---- normalize + write bf16 hi/lo ----
    const float inv_a = (l_a > 0.f) ? 1.f / l_a : 0.f;
    const float inv_b = (l_b > 0.f) ? 1.f / l_b : 0.f;
    #pragma unroll
    for (int ni = 0; ni < 8; ni++) {
        const int d = h * 64 + ni * 8 + (lane & 3) * 2;
        uint32_t h0, l0, h1, l1;
        split2(oacc[ni][0] * inv_a, oacc[ni][1] * inv_a, h0, l0);
        split2(oacc[ni][2] * inv_b, oacc[ni][3] * inv_b, h1, l1);
        *(uint32_t*)(ahi + (size_t)ra * EDIM + d) = h0;
        *(uint32_t*)(alo + (size_t)ra * EDIM + d) = l0;
        *(uint32_t*)(ahi + (size_t)rb * EDIM + d) = h1;
        *(uint32_t*)(alo + (size_t)rb * EDIM + d) = l1;
    }
}

// ---------------------------------------------------------------------------
extern "C" void kernel_launch(void* const* d_in, const int* in_sizes, int n_in,
                              void* d_out, int out_size)
{
    const float* x    = (const float*)d_in[0];
    const float* Wqkv = (const float*)d_in[1];
    const float* bqkv = (const float*)d_in[2];
    const float* Wo   = (const float*)d_in[3];
    const float* bo   = (const float*)d_in[4];
    float* out = (float*)d_out;

    __nv_bfloat16 *xhi, *xlo, *wqhi, *wqlo, *wohi, *wolo, *qkvhi, *qkvlo, *ahi, *alo;
    cudaGetSymbolAddress((void**)&xhi,   g_xhi);
    cudaGetSymbolAddress((void**)&xlo,   g_xlo);
    cudaGetSymbolAddress((void**)&wqhi,  g_wqhi);
    cudaGetSymbolAddress((void**)&wqlo,  g_wqlo);
    cudaGetSymbolAddress((void**)&wohi,  g_wohi);
    cudaGetSymbolAddress((void**)&wolo,  g_wolo);
    cudaGetSymbolAddress((void**)&qkvhi, g_qkvhi);
    cudaGetSymbolAddress((void**)&qkvlo, g_qkvlo);
    cudaGetSymbolAddress((void**)&ahi,   g_ahi);
    cudaGetSymbolAddress((void**)&alo,   g_alo);

    const int GEMM_SMEM = 2 * BUFB;
    cudaFuncSetAttribute(gemm_tc_kernel, cudaFuncAttributeMaxDynamicSharedMemorySize, GEMM_SMEM);
    cudaFuncSetAttribute(attn_tc_kernel, cudaFuncAttributeMaxDynamicSharedMemorySize, ATTN_SMEM);

    {
        int n4 = (S_LEN * EDIM) / 4;
        split_bf16_kernel<<<(n4 + 255) / 256, 256>>>(
            (const float4*)x, (__nv_bfloat162*)xhi, (__nv_bfloat162*)xlo, n4);
    }
    {
        int n4 = (QKVN * EDIM) / 4;
        split_bf16_kernel<<<(n4 + 255) / 256, 256>>>(
            (const float4*)Wqkv, (__nv_bfloat162*)wqhi, (__nv_bfloat162*)wqlo, n4);
    }
    {
        int n4 = (EDIM * EDIM) / 4;
        split_bf16_kernel<<<(n4 + 255) / 256, 256>>>(
            (const float4*)Wo, (__nv_bfloat162*)wohi, (__nv_bfloat162*)wolo, n4);
    }

    // 1) QKV projection -> bf16 hi/lo
    gemm_tc_kernel<<<dim3(QKVN / 128, S_LEN / 128), 256, GEMM_SMEM>>>(
        xhi, xlo, wqhi, wqlo, bqkv, nullptr, qkvhi, qkvlo, S_LEN, QKVN, EDIM);

    // 2) flash attention on tensor cores -> bf16 hi/lo
    attn_tc_kernel<<<dim3(S_LEN / 64, NH), 128, ATTN_SMEM>>>(qkvhi, qkvlo, ahi, alo);

    // 3) output projection -> fp32 out
    gemm_tc_kernel<<<dim3(EDIM / 128, S_LEN / 128), 256, GEMM_SMEM>>>(
        ahi, alo, wohi, wolo, bo, out, nullptr, nullptr, S_LEN, EDIM, EDIM);
}